// round 17
// baseline (speedup 1.0000x reference)
#include <cuda_runtime.h>
#include <cuda_bf16.h>
#include <cuda_fp16.h>
#include <math.h>
#include <stdint.h>

#define S_LEN 2048
#define EMB   2048
#define NHEAD 16
#define HDIM  128

// ---------------- scratch (no cudaMalloc allowed) ----------------
__device__ __align__(256) __half g_px [S_LEN * EMB];
__device__ __align__(256) __half g_pao[S_LEN * EMB];
__device__ __align__(256) __half g_pwq[EMB * EMB];
__device__ __align__(256) __half g_pwk[EMB * EMB];
__device__ __align__(256) __half g_pwv[EMB * EMB];
__device__ __align__(256) __half g_pwo[EMB * EMB];

__device__ __half g_qh [S_LEN * EMB];   // q (scaled by log2e/sqrt(d))
__device__ __half g_kh [S_LEN * EMB];
__device__ __half g_vth[NHEAD * HDIM * S_LEN];   // [h][d][s]

// ================= helpers (baseline PTX only) ==============
__device__ __forceinline__ uint32_t s2u(const void* p) {
    uint32_t a;
    asm("{ .reg .u64 t; cvta.to.shared.u64 t, %1; cvt.u32.u64 %0, t; }"
        : "=r"(a) : "l"(p));
    return a;
}

__device__ __forceinline__ void cpa16(uint32_t dst, const void* src) {
    asm volatile("cp.async.cg.shared.global [%0], [%1], 16;" :: "r"(dst), "l"(src));
}
#define CPA_COMMIT() asm volatile("cp.async.commit_group;" ::: "memory")
#define CPA_WAIT1()  asm volatile("cp.async.wait_group 1;" ::: "memory")

__device__ __forceinline__ void ldsm4(uint32_t addr, uint32_t& r0, uint32_t& r1,
                                      uint32_t& r2, uint32_t& r3) {
    asm volatile("ldmatrix.sync.aligned.m8n8.x4.shared.b16 {%0,%1,%2,%3}, [%4];"
                 : "=r"(r0), "=r"(r1), "=r"(r2), "=r"(r3) : "r"(addr));
}

__device__ __forceinline__ void mma_f16(float* d, const uint32_t* a,
                                        uint32_t b0, uint32_t b1) {
    asm volatile(
        "mma.sync.aligned.m16n8k16.row.col.f32.f16.f16.f32 "
        "{%0,%1,%2,%3}, {%4,%5,%6,%7}, {%8,%9}, {%0,%1,%2,%3};"
        : "+f"(d[0]), "+f"(d[1]), "+f"(d[2]), "+f"(d[3])
        : "r"(a[0]), "r"(a[1]), "r"(a[2]), "r"(a[3]), "r"(b0), "r"(b1));
}

__device__ __forceinline__ uint32_t h2u(__half2 v) {
    return *reinterpret_cast<uint32_t*>(&v);
}

__device__ __forceinline__ uint32_t exp2_f16x2(float a, float b) {
    uint32_t packed, r;
    asm("cvt.rn.f16x2.f32 %0, %1, %2;" : "=r"(packed) : "f"(b), "f"(a));
    asm("ex2.approx.f16x2 %0, %1;" : "=r"(r) : "r"(packed));
    return r;
}

// ---- mbarrier / bulk-copy (sm_90 baseline PTX) ----
#define MBAR_INIT(mbar, cnt) \
    asm volatile("mbarrier.init.shared.b64 [%0], %1;" \
                 :: "r"((uint32_t)(mbar)), "r"((uint32_t)(cnt)) : "memory")
#define MBAR_EXPECT_TX(mbar, bytes) \
    asm volatile("mbarrier.arrive.expect_tx.shared.b64 _, [%0], %1;" \
                 :: "r"((uint32_t)(mbar)), "r"((uint32_t)(bytes)) : "memory")
#define MBAR_ARRIVE(mbar) \
    asm volatile("mbarrier.arrive.shared.b64 _, [%0];" \
                 :: "r"((uint32_t)(mbar)) : "memory")

__device__ __forceinline__ void mbar_wait(uint32_t mbar, uint32_t phase) {
    asm volatile(
        "{\n\t.reg .pred P1;\n\t"
        "WAIT_LOOP_%=:\n\t"
        "mbarrier.try_wait.parity.acquire.cta.shared::cta.b64 P1, [%0], %1, 0x989680;\n\t"
        "@P1 bra.uni WAIT_DONE_%=;\n\t"
        "bra.uni WAIT_LOOP_%=;\n\t"
        "WAIT_DONE_%=:\n\t}"
        :: "r"(mbar), "r"(phase) : "memory");
}

__device__ __forceinline__ void bulkcp(uint32_t dst, const void* src,
                                       uint32_t bytes, uint32_t mbar) {
    asm volatile(
        "cp.async.bulk.shared::cluster.global.mbarrier::complete_tx::bytes "
        "[%0], [%1], %2, [%3];"
        :: "r"(dst), "l"(src), "r"(bytes), "r"(mbar) : "memory");
}

// ================= repack fp32 -> fp16, stage-contiguous + XOR swizzle ====
__device__ __forceinline__ void pack_row(
    const float* __restrict__ src, __half* __restrict__ dst, int r, int t)
{
    const int ks  = t >> 3;
    const int cs  = t & 7;
    const int rin = r & 127;
    const int blk = r >> 7;
    const int c   = cs ^ (rin & 7);

    const float* s = src + (size_t)r * EMB + ks * 64 + c * 8;
    float4 v0 = *(const float4*)(s);
    float4 v1 = *(const float4*)(s + 4);

    __half2 h0 = __floats2half2_rn(v0.x, v0.y);
    __half2 h1 = __floats2half2_rn(v0.z, v0.w);
    __half2 h2 = __floats2half2_rn(v1.x, v1.y);
    __half2 h3 = __floats2half2_rn(v1.z, v1.w);

    size_t chunk = ((size_t)(blk * 32 + ks) * 128 + rin) * 8 + cs;
    uint4 out;
    out.x = h2u(h0); out.y = h2u(h1); out.z = h2u(h2); out.w = h2u(h3);
    *(reinterpret_cast<uint4*>(dst) + chunk) = out;
}

__global__ __launch_bounds__(256) void conv_pack_all(
    const float* __restrict__ x,
    const float* __restrict__ w0, const float* __restrict__ w1,
    const float* __restrict__ w2, const float* __restrict__ w3,
    __half* __restrict__ dx,
    __half* __restrict__ d0, __half* __restrict__ d1,
    __half* __restrict__ d2, __half* __restrict__ d3)
{
    const float* s;
    __half* d;
    switch (blockIdx.y) {
        case 0: s = x;  d = dx; break;
        case 1: s = w0; d = d0; break;
        case 2: s = w1; d = d1; break;
        case 3: s = w2; d = d2; break;
        default: s = w3; d = d3; break;
    }
    pack_row(s, d, blockIdx.x, threadIdx.x);
}

// ================= TMA-bulk fp16 GEMM: CTA 64x128, 3 CTAs/SM ==============
// 8 warps (2x4), warp tile 32x32. K staged 64; 3-slot ring. smem 72KB.
#define GB_A_BYTES 8192
#define GB_B_BYTES 16384
#define GB_STAGE   24576
#define GB_SMEM    (3 * GB_STAGE + 128)

// C tile: rows [by*64, by*64+64), cols [bx*128, bx*128+128)
__device__ __forceinline__ void gemm_main64(
    const __half* __restrict__ Ap, const __half* __restrict__ Bp,
    int bx, int by, float acc[2][4][4])
{
    extern __shared__ char smraw[];
    const uint32_t sbase = s2u(smraw);
    const uint32_t mb    = sbase + 3 * GB_STAGE;

    const int tid  = threadIdx.x;
    const int lane = tid & 31;
    const int wid  = tid >> 5;
    const int wm   = wid & 1;        // 32-row group
    const int wn   = wid >> 1;       // 0..3, 32-col group

    const int l8 = lane & 7;
    const int mt = lane >> 3;

    int rA[2], rB[2];
#pragma unroll
    for (int i = 0; i < 2; i++)
        rA[i] = wm * 32 + i * 16 + (mt & 1) * 8 + l8;
#pragma unroll
    for (int j = 0; j < 2; j++)
        rB[j] = wn * 32 + j * 16 + (mt >> 1) * 8 + l8;
    const int hcA = mt >> 1;
    const int hcB = mt & 1;

#pragma unroll
    for (int i = 0; i < 2; i++)
#pragma unroll
        for (int j = 0; j < 4; j++)
#pragma unroll
            for (int t = 0; t < 4; t++) acc[i][j][t] = 0.f;

    if (tid == 0) {
#pragma unroll
        for (int i = 0; i < 3; i++) {
            MBAR_INIT(mb + i * 16, 1);
            MBAR_INIT(mb + i * 16 + 8, 8);
        }
    }
    __syncthreads();

    // packed layout: [blk128][ks][rin128][chunk8]; 64-row slice contiguous.
    const __half* Asrc = Ap + (size_t)(by >> 1) * 32 * 128 * 64
                            + (size_t)(by & 1) * 64 * 64;
    const __half* Bsrc = Bp + (size_t)bx * 32 * 128 * 64;

    if (tid == 0) {
#pragma unroll
        for (int i = 0; i < 3; i++) {
            MBAR_EXPECT_TX(mb + i * 16, GB_STAGE);
            bulkcp(sbase + i * GB_STAGE, Asrc + (size_t)i * 128 * 64,
                   GB_A_BYTES, mb + i * 16);
            bulkcp(sbase + i * GB_STAGE + GB_A_BYTES, Bsrc + (size_t)i * 128 * 64,
                   GB_B_BYTES, mb + i * 16);
        }
    }

    const int NST = EMB / 64;
    for (int s = 0; s < NST; s++) {
        const int sl = s - (s / 3) * 3;
        const uint32_t ph = (uint32_t)((s / 3) & 1);
        const uint32_t slot = sbase + sl * GB_STAGE;

        mbar_wait(mb + sl * 16, ph);

#pragma unroll
        for (int ks = 0; ks < 4; ks++) {
            uint32_t a[2][4];
#pragma unroll
            for (int i = 0; i < 2; i++) {
                uint32_t ch = (uint32_t)((2 * ks + hcA) ^ (rA[i] & 7));
                ldsm4(slot + rA[i] * 128 + ch * 16,
                      a[i][0], a[i][1], a[i][2], a[i][3]);
            }
            uint32_t b[2][4];
#pragma unroll
            for (int j = 0; j < 2; j++) {
                uint32_t ch = (uint32_t)((2 * ks + hcB) ^ (rB[j] & 7));
                ldsm4(slot + GB_A_BYTES + rB[j] * 128 + ch * 16,
                      b[j][0], b[j][1], b[j][2], b[j][3]);
            }
#pragma unroll
            for (int i = 0; i < 2; i++)
#pragma unroll
                for (int j = 0; j < 2; j++) {
                    mma_f16(acc[i][j * 2 + 0], a[i], b[j][0], b[j][1]);
                    mma_f16(acc[i][j * 2 + 1], a[i], b[j][2], b[j][3]);
                }
        }

        if (lane == 0) MBAR_ARRIVE(mb + sl * 16 + 8);

        if (tid == 0 && s + 3 < NST) {
            mbar_wait(mb + sl * 16 + 8, ph);
            MBAR_EXPECT_TX(mb + sl * 16, GB_STAGE);
            bulkcp(slot, Asrc + (size_t)(s + 3) * 128 * 64,
                   GB_A_BYTES, mb + sl * 16);
            bulkcp(slot + GB_A_BYTES, Bsrc + (size_t)(s + 3) * 128 * 64,
                   GB_B_BYTES, mb + sl * 16);
        }
    }
}

// ---- Wo GEMM: plain fp32 epilogue ----
__global__ __launch_bounds__(256, 3) void gemm_bulk(
    const __half* __restrict__ Ap, const __half* __restrict__ Bp,
    float* __restrict__ C)
{
    float acc[2][4][4];
    gemm_main64(Ap, Bp, blockIdx.x, blockIdx.y, acc);

    const int tid  = threadIdx.x;
    const int lane = tid & 31;
    const int wid  = tid >> 5;
    const int wm   = wid & 1;
    const int wn   = wid >> 1;
    const int bm   = blockIdx.y * 64;
    const int bn   = blockIdx.x * 128;
    const int g = lane >> 2;
    const int q = (lane & 3) * 2;
#pragma unroll
    for (int i = 0; i < 2; i++) {
#pragma unroll
        for (int j = 0; j < 4; j++) {
            int row = bm + wm * 32 + i * 16 + g;
            int col = bn + wn * 32 + j * 8 + q;
            *(float2*)(C + (size_t)row * EMB + col) =
                make_float2(acc[i][j][0], acc[i][j][1]);
            *(float2*)(C + (size_t)(row + 8) * EMB + col) =
                make_float2(acc[i][j][2], acc[i][j][3]);
        }
    }
}

// ---- fused QKV GEMM: 64x128 tile (full head cols). RoPE / V-transpose ----
#define EP_STRIDE 129

__global__ __launch_bounds__(256, 3) void gemm_qkv_fused(
    const __half* __restrict__ Ap,
    const __half* __restrict__ Bq, const __half* __restrict__ Bk,
    const __half* __restrict__ Bv,
    const float* __restrict__ cosb, const float* __restrict__ sinb,
    __half* __restrict__ qh, __half* __restrict__ kh,
    __half* __restrict__ vth)
{
    const int z = blockIdx.z;
    const __half* Bp = (z == 0) ? Bq : (z == 1) ? Bk : Bv;

    float acc[2][4][4];
    gemm_main64(Ap, Bp, blockIdx.x, blockIdx.y, acc);

    extern __shared__ char smraw[];
    float* smf = reinterpret_cast<float*>(smraw);

    const int tid  = threadIdx.x;
    const int lane = tid & 31;
    const int wid  = tid >> 5;
    const int wm   = wid & 1;
    const int wn   = wid >> 1;
    const int bm   = blockIdx.y * 64;
    const int h    = blockIdx.x;
    const int g = lane >> 2;
    const int q = (lane & 3) * 2;

    __syncthreads();

    // stage acc in smem [64 rows][EP_STRIDE]
#pragma unroll
    for (int i = 0; i < 2; i++) {
#pragma unroll
        for (int j = 0; j < 4; j++) {
            int row = wm * 32 + i * 16 + g;
            int col = wn * 32 + j * 8 + q;
            smf[row * EP_STRIDE + col]           = acc[i][j][0];
            smf[row * EP_STRIDE + col + 1]       = acc[i][j][1];
            smf[(row + 8) * EP_STRIDE + col]     = acc[i][j][2];
            smf[(row + 8) * EP_STRIDE + col + 1] = acc[i][j][3];
        }
    }
    __syncthreads();

    if (z < 2) {
        __half* dst = (z == 0) ? qh : kh;
        const float sc = (z == 0) ? 0.12751744f : 1.f;   // 1/sqrt(d)*log2(e)
        const int c    = tid & 127;
        const int shal = tid >> 7;
        const bool low = c < 64;
#pragma unroll 4
        for (int si = 0; si < 32; si++) {
            int s = shal * 32 + si;
            float a = smf[s * EP_STRIDE + c];
            float b = smf[s * EP_STRIDE + (c ^ 64)];
            int srow = bm + s;
            float cv = cosb[srow * HDIM + c];
            float sv = sinb[srow * HDIM + c];
            float out = (low ? (a * cv - b * sv) : (a * cv + b * sv)) * sc;
            dst[(size_t)srow * EMB + h * HDIM + c] = __float2half_rn(out);
        }
    } else {
        const int c0 = wid * 16;
#pragma unroll 4
        for (int cc = 0; cc < 16; cc++) {
            int d = c0 + cc;
            size_t rowbase = ((size_t)(h * HDIM + d)) * S_LEN + bm;
#pragma unroll
            for (int s4 = 0; s4 < 2; s4++) {
                int s = s4 * 32 + lane;
                vth[rowbase + s] = __float2half_rn(smf[s * EP_STRIDE + d]);
            }
        }
    }
}

// ---------------- Flash attention v2: 128-thr CTA, 64 q-rows, 2 CTAs/SM ---
#define QB_ROW  272
#define KB_ROW  272
#define VB_ROW  272
#define SM_Q    (64 * QB_ROW)
#define SM_K    (128 * KB_ROW)
#define SM_V    (128 * VB_ROW)
#define FA_SMEM (SM_Q + SM_K + SM_V)    // 87040 -> 2 CTAs/SM

__global__ __launch_bounds__(128, 2) void flash_mma(
    const __half* __restrict__ qh, const __half* __restrict__ kh,
    const __half* __restrict__ vth,
    __half* __restrict__ pao)
{
    extern __shared__ char smraw[];
    const uint32_t sQ = s2u(smraw);
    const uint32_t sK = sQ + SM_Q;
    const uint32_t sV = sK + SM_K;

    const int tid  = threadIdx.x;
    const int lane = tid & 31;
    const int w    = tid >> 5;
    const int g    = lane >> 2;
    const int qd   = lane & 3;
    const int l8   = lane & 7;
    const int mt   = lane >> 3;
    const int qbi  = gridDim.x - 1 - blockIdx.x;
    const int h    = blockIdx.y;

    const uint32_t ONES = 0x3C003C00u;

    const uint32_t offAq = (uint32_t)((w * 16 + (mt & 1) * 8 + l8) * QB_ROW + (mt >> 1) * 16);
    uint32_t offBk[8], offBv[8];
#pragma unroll
    for (int j = 0; j < 8; j++)
        offBk[j] = (uint32_t)((j * 16 + (mt >> 1) * 8 + l8) * KB_ROW + (mt & 1) * 16);
#pragma unroll
    for (int j = 0; j < 8; j++)
        offBv[j] = (uint32_t)((j * 16 + (mt >> 1) * 8 + l8) * VB_ROW + (mt & 1) * 16);

#pragma unroll
    for (int i = 0; i < 8; i++) {
        int e = tid + i * 128;
        int r = (e >> 4) & 63;
        int c = e & 15;
        const __half* s = qh + (size_t)(qbi * 64 + r) * EMB + h * HDIM + c * 8;
        cpa16(sQ + r * QB_ROW + c * 16, s);
    }

    auto load_k = [&](int kb) {
#pragma unroll
        for (int i = 0; i < 16; i++) {
            int e = tid + i * 128;
            int r = (e >> 4) & 127;
            int c = e & 15;
            const __half* s = kh + (size_t)(kb * 128 + r) * EMB + h * HDIM + c * 8;
            cpa16(sK + r * KB_ROW + c * 16, s);
        }
    };
    auto load_v = [&](int kb) {
#pragma unroll
        for (int i = 0; i < 16; i++) {
            int e = tid + i * 128;
            int r = (e >> 4) & 127;
            int c = e & 15;
            const __half* s = vth + (size_t)(h * HDIM + r) * S_LEN + kb * 128 + c * 8;
            cpa16(sV + r * VB_ROW + c * 16, s);
        }
    };

    const int nkb = (qbi >> 1) + 1;
    load_k(0);
    CPA_COMMIT();
    load_v(0);
    CPA_COMMIT();

    float acco[16][4];
#pragma unroll
    for (int j = 0; j < 16; j++)
#pragma unroll
        for (int t = 0; t < 4; t++) acco[j][t] = 0.f;
    float lacc[4] = {0.f, 0.f, 0.f, 0.f};
    float m0 = -1e30f, m8 = -1e30f;

    const int row0 = qbi * 64 + w * 16 + g;
    const int row8 = row0 + 8;

    for (int kb = 0; kb < nkb; kb++) {
        CPA_WAIT1();
        __syncthreads();

        float accs[16][4];
#pragma unroll
        for (int j = 0; j < 16; j++)
#pragma unroll
            for (int t = 0; t < 4; t++) accs[j][t] = 0.f;

#pragma unroll
        for (int ks = 0; ks < 8; ks++) {
            uint32_t a[4];
            ldsm4(sQ + offAq + ks * 32, a[0], a[1], a[2], a[3]);
#pragma unroll
            for (int j = 0; j < 8; j++) {
                uint32_t b0, b1, b2, b3;
                ldsm4(sK + offBk[j] + ks * 32, b0, b1, b2, b3);
                mma_f16(accs[j * 2 + 0], a, b0, b1);
                mma_f16(accs[j * 2 + 1], a, b2, b3);
            }
        }
        __syncthreads();

        if (kb + 1 < nkb) load_k(kb + 1);
        CPA_COMMIT();

        if (kb == nkb - 1) {
#pragma unroll
            for (int jt = 0; jt < 16; jt++) {
                int col = kb * 128 + jt * 8 + 2 * qd;
                if (col     > row0) accs[jt][0] = -1e30f;
                if (col + 1 > row0) accs[jt][1] = -1e30f;
                if (col     > row8) accs[jt][2] = -1e30f;
                if (col + 1 > row8) accs[jt][3] = -1e30f;
            }
        }

        float mx0 = -1e30f, mx8 = -1e30f;
#pragma unroll
        for (int jt = 0; jt < 16; jt++) {
            mx0 = fmaxf(mx0, fmaxf(accs[jt][0], accs[jt][1]));
            mx8 = fmaxf(mx8, fmaxf(accs[jt][2], accs[jt][3]));
        }
        mx0 = fmaxf(mx0, __shfl_xor_sync(0xffffffffu, mx0, 1));
        mx0 = fmaxf(mx0, __shfl_xor_sync(0xffffffffu, mx0, 2));
        mx8 = fmaxf(mx8, __shfl_xor_sync(0xffffffffu, mx8, 1));
        mx8 = fmaxf(mx8, __shfl_xor_sync(0xffffffffu, mx8, 2));

        float nm0 = fmaxf(m0, mx0), nm8 = fmaxf(m8, mx8);
        bool nochg = (nm0 == m0) && (nm8 == m8);
        bool allno = __all_sync(0xffffffffu, nochg);
        if (!allno) {
            float al0 = exp2f(m0 - nm0);
            float al8 = exp2f(m8 - nm8);
#pragma unroll
            for (int j = 0; j < 16; j++) {
                acco[j][0] *= al0; acco[j][1] *= al0;
                acco[j][2] *= al8; acco[j][3] *= al8;
            }
            lacc[0] *= al0; lacc[1] *= al0;
            lacc[2] *= al8; lacc[3] *= al8;
        }
        m0 = nm0; m8 = nm8;

        uint32_t pf[16][2];
#pragma unroll
        for (int jt = 0; jt < 16; jt++) {
            pf[jt][0] = exp2_f16x2(accs[jt][0] - nm0, accs[jt][1] - nm0);
            pf[jt][1] = exp2_f16x2(accs[jt][2] - nm8, accs[jt][3] - nm8);
        }

        CPA_WAIT1();
        __syncthreads();

#pragma unroll
        for (int t = 0; t < 8; t++) {
            uint32_t a[4];
            a[0] = pf[2 * t][0]; a[1] = pf[2 * t][1];
            a[2] = pf[2 * t + 1][0]; a[3] = pf[2 * t + 1][1];
            mma_f16(lacc, a, ONES, ONES);
#pragma unroll
            for (int jn = 0; jn < 8; jn++) {
                uint32_t b0, b1, b2, b3;
                ldsm4(sV + offBv[jn] + t * 32, b0, b1, b2, b3);
                mma_f16(acco[jn * 2 + 0], a, b0, b1);
                mma_f16(acco[jn * 2 + 1], a, b2, b3);
            }
        }
        __syncthreads();

        if (kb + 1 < nkb) load_v(kb + 1);
        CPA_COMMIT();
    }

    float inv0 = 1.f / lacc[0], inv8 = 1.f / lacc[2];
    const int blk  = row0 >> 7;
    const int rin0 = row0 & 127;
    const int rin8 = row8 & 127;
#pragma unroll
    for (int jt = 0; jt < 16; jt++) {
        int ks = h * 2 + (jt >> 3);
        int c8 = jt & 7;
        size_t chunk0 = ((size_t)(blk * 32 + ks) * 128 + rin0) * 8 + (c8 ^ (rin0 & 7));
        size_t chunk8 = ((size_t)(blk * 32 + ks) * 128 + rin8) * 8 + (c8 ^ (rin8 & 7));
        __half2 v0 = __floats2half2_rn(acco[jt][0] * inv0, acco[jt][1] * inv0);
        __half2 v8 = __floats2half2_rn(acco[jt][2] * inv8, acco[jt][3] * inv8);
        *reinterpret_cast<__half2*>(pao + chunk0 * 8 + qd * 2) = v0;
        *reinterpret_cast<__half2*>(pao + chunk8 * 8 + qd * 2) = v8;
    }
}

// ---------------- launch ----------------
extern "C" void kernel_launch(void* const* d_in, const int* in_sizes, int n_in,
                              void* d_out, int out_size)
{
    const float* x  = (const float*)d_in[0];
    const float* rc = (const float*)d_in[1];
    const float* rs = (const float*)d_in[2];
    const float* Wq = (const float*)d_in[3];
    const float* Wk = (const float*)d_in[4];
    const float* Wv = (const float*)d_in[5];
    const float* Wo = (const float*)d_in[6];
    float* out = (float*)d_out;

    __half *px, *pao, *pwq, *pwk, *pwv, *pwo;
    cudaGetSymbolAddress((void**)&px,  g_px);
    cudaGetSymbolAddress((void**)&pao, g_pao);
    cudaGetSymbolAddress((void**)&pwq, g_pwq);
    cudaGetSymbolAddress((void**)&pwk, g_pwk);
    cudaGetSymbolAddress((void**)&pwv, g_pwv);
    cudaGetSymbolAddress((void**)&pwo, g_pwo);

    __half *qh, *kh, *vth;
    cudaGetSymbolAddress((void**)&qh,  g_qh);
    cudaGetSymbolAddress((void**)&kh,  g_kh);
    cudaGetSymbolAddress((void**)&vth, g_vth);

    cudaFuncSetAttribute(gemm_bulk,
                         cudaFuncAttributeMaxDynamicSharedMemorySize, GB_SMEM);
    cudaFuncSetAttribute(gemm_qkv_fused,
                         cudaFuncAttributeMaxDynamicSharedMemorySize, GB_SMEM);
    cudaFuncSetAttribute(flash_mma,
                         cudaFuncAttributeMaxDynamicSharedMemorySize, FA_SMEM);

    // repack inputs (x + 4 weights in one launch)
    conv_pack_all<<<dim3(EMB, 5), 256>>>(x, Wq, Wk, Wv, Wo,
                                         px, pwq, pwk, pwv, pwo);

    // fused QKV projection + RoPE/transpose epilogue (1536 CTAs, 3/SM)
    dim3 gq(EMB / 128, S_LEN / 64, 3);
    gemm_qkv_fused<<<gq, 256, GB_SMEM>>>(px, pwq, pwk, pwv, rc, rs,
                                         qh, kh, vth);

    // flash attention (512 CTAs of 64 q-rows, 2/SM) -> packed fp16 pao
    flash_mma<<<dim3(S_LEN / 64, NHEAD), 128, FA_SMEM>>>(qh, kh, vth, pao);

    // output projection (512 CTAs, 3/SM)
    dim3 gg(EMB / 128, S_LEN / 64);
    gemm_bulk<<<gg, 256, GB_SMEM>>>(pao, pwo, out);
}